// round 8
// baseline (speedup 1.0000x reference)
#include <cuda_runtime.h>
#include <cstdint>

#define BATCH  256
#define EDIM   512
#define NNODES 16383
#define NPAD   16384

// Quantization scales: x in [-6,6], dW in [-0.45,0.45] (7.2 sigma), 16-bit grids
#define QMAX   32639
#define SX_F   (32639.0f / 6.0f)
#define SW_F   (32639.0f / 0.45f)
#define INV_F  2.534490e-9f   // (6*0.45)/(32639^2)

// ---------------------------------------------------------------------------
// Scratch (static device globals: allocation-free rule)
// ---------------------------------------------------------------------------
__device__ __align__(16) char g_Ah[BATCH * EDIM];   // hi digits of x16
__device__ __align__(16) char g_Al[BATCH * EDIM];   // lo digits
__device__ float g_S[BATCH * NPAD];                 // delta logits

// ---------------------------------------------------------------------------
// Prep: quantize x to int16, split into s8 digits
// ---------------------------------------------------------------------------
__device__ __forceinline__ void quant_split(float v, float scale, int& h, int& l) {
    int q = __float2int_rn(v * scale);
    q = max(-QMAX, min(QMAX, q));
    h = (q + 128) >> 8;          // in [-128, 127]
    l = q - (h << 8);            // in [-128, 127]
}

__global__ void prep_kernel(const float* __restrict__ x) {
    int idx = blockIdx.x * blockDim.x + threadIdx.x;   // 0..32767 float4
    int b  = idx >> 7;
    int e4 = (idx & 127) * 4;
    float4 v = reinterpret_cast<const float4*>(x)[idx];
    int h0, l0, h1, l1, h2, l2, h3, l3;
    quant_split(v.x, SX_F, h0, l0);
    quant_split(v.y, SX_F, h1, l1);
    quant_split(v.z, SX_F, h2, l2);
    quant_split(v.w, SX_F, h3, l3);
    char4 hc = make_char4((char)h0, (char)h1, (char)h2, (char)h3);
    char4 lc = make_char4((char)l0, (char)l1, (char)l2, (char)l3);
    *reinterpret_cast<char4*>(g_Ah + b * EDIM + e4) = hc;
    *reinterpret_cast<char4*>(g_Al + b * EDIM + e4) = lc;
}

// ---------------------------------------------------------------------------
// cp.async + ldmatrix + IMMA helpers (sm_75/80 baseline ISA)
// ---------------------------------------------------------------------------
__device__ __forceinline__ uint32_t smem_u32(const void* p) {
    uint32_t a;
    asm("{ .reg .u64 t; cvta.to.shared.u64 t, %1; cvt.u32.u64 %0, t; }" : "=r"(a) : "l"(p));
    return a;
}
__device__ __forceinline__ void cp16(uint32_t dst, const void* src) {
    asm volatile("cp.async.ca.shared.global [%0], [%1], 16;" :: "r"(dst), "l"(src));
}
__device__ __forceinline__ void cp16z(uint32_t dst, const void* src, uint32_t src_bytes) {
    asm volatile("cp.async.ca.shared.global [%0], [%1], 16, %2;"
                 :: "r"(dst), "l"(src), "r"(src_bytes));
}
#define CP_COMMIT() asm volatile("cp.async.commit_group;" ::: "memory")
#define CP_WAIT0()  asm volatile("cp.async.wait_group 0;" ::: "memory")

__device__ __forceinline__ void ldsm4(uint32_t* r, uint32_t addr) {
    asm volatile("ldmatrix.sync.aligned.m8n8.x4.shared.b16 {%0,%1,%2,%3}, [%4];"
                 : "=r"(r[0]), "=r"(r[1]), "=r"(r[2]), "=r"(r[3]) : "r"(addr));
}
__device__ __forceinline__ void ldsm2(uint32_t* r, uint32_t addr) {
    asm volatile("ldmatrix.sync.aligned.m8n8.x2.shared.b16 {%0,%1}, [%2];"
                 : "=r"(r[0]), "=r"(r[1]) : "r"(addr));
}

// mma m16n8k32 s8*s8 -> s32
__device__ __forceinline__ void imma(int* d, const uint32_t* a, uint32_t b0, uint32_t b1) {
    asm volatile(
        "mma.sync.aligned.m16n8k32.row.col.s32.s8.s8.s32 "
        "{%0,%1,%2,%3}, {%4,%5,%6,%7}, {%8,%9}, {%0,%1,%2,%3};\n"
        : "+r"(d[0]), "+r"(d[1]), "+r"(d[2]), "+r"(d[3])
        : "r"(a[0]), "r"(a[1]), "r"(a[2]), "r"(a[3]), "r"(b0), "r"(b1));
}

// ---------------------------------------------------------------------------
// int8 GEMM, fused W quantize.  Block: M=256 x N=32.  512 thr / 16 warps,
// warp tile 64(M) x 8(N).  K = 512 in 16 chunks of 32.
// Terms: 65536*hh + 256*(hl+lh) + ll, exact s32, combined in s64.
// Rows of 32 int8 at pitch 48 (48r mod 128 covers all 16B segments once
// -> conflict-free ldmatrix).
// ---------------------------------------------------------------------------
#define NB       32
#define P48      48
#define OFF_AH_  0                  // 256 x 48 = 12288
#define OFF_AL_  12288
#define OFF_BH_  24576              // 32 x 48 = 1536
#define OFF_BL_  26112
#define OFF_WR_  27648              // raw W: 32 nodes x 64 floats = 8192
#define STAGE_I8 35840
#define OFF_DB_  (2 * STAGE_I8)     // 71680
#define GEMM_SMEM (OFF_DB_ + 128)   // 71808

__global__ void __launch_bounds__(512) gemm_i8(const float* __restrict__ W,
                                               const float* __restrict__ bvec) {
    extern __shared__ char smem[];
    const uint32_t sb = smem_u32(smem);
    const int tid  = threadIdx.x;
    const int lane = tid & 31;
    const int warp = tid >> 5;
    const int wm   = warp >> 2;   // 0..3 -> M base wm*64
    const int wn   = warp & 3;    // 0..3 -> N base wn*8
    const int nbase = blockIdx.x * NB;

    float* db_s = reinterpret_cast<float*>(smem + OFF_DB_);
    if (tid < NB) {
        int col = nbase + tid;
        db_s[tid] = (col < NNODES) ? (bvec[2 * col + 1] - bvec[2 * col]) : 0.f;
    }

    int hh[4][4], mid[4][4], ll[4][4];
#pragma unroll
    for (int mi = 0; mi < 4; ++mi)
#pragma unroll
        for (int q = 0; q < 4; ++q) { hh[mi][q] = 0; mid[mi][q] = 0; ll[mi][q] = 0; }

    // ldmatrix lane->address components
    // A m16k32 tile: groups (r0-7,kb0)(r8-15,kb0)(r0-7,kb16)(r8-15,kb16)
    const int a_lrow = (lane & 7) + 8 * ((lane >> 3) & 1);
    const int a_lkb  = 16 * (lane >> 4);
    // B n8k32 tile (x2): groups (n0-7,kb0)(n0-7,kb16); lanes >=16 unused
    const int bl_    = lane & 15;
    const int b_lrow = wn * 8 + (bl_ & 7);
    const int b_lkb  = 16 * (bl_ >> 3);

    // ---- issue async loads for chunk c into stage c&1 ----
    auto issue = [&](int c) {
        const uint32_t stg = sb + (uint32_t)(c & 1) * STAGE_I8;
        // A digits: 256 rows x 32 B x {hi,lo} = 1024 cp16, 2/thread
#pragma unroll
        for (int j = 0; j < 2; ++j) {
            int u = tid + 512 * j;
            int arr = u >> 9;          // 0=hi, 1=lo
            int v = u & 511;
            int row = v >> 1;
            int half = v & 1;
            const char* base = arr ? g_Al : g_Ah;
            cp16(stg + (arr ? OFF_AL_ : OFF_AH_) + row * P48 + half * 16,
                 base + row * EDIM + c * 32 + half * 16);
        }
        // raw W: 32 nodes x 64 floats = 512 cp16, 1/thread
        {
            int p  = tid;
            int nl = p >> 4;
            int e2 = p & 15;
            int ng = nbase + nl;
            int ok = (ng < NNODES);
            const char* src = reinterpret_cast<const char*>(
                W + (size_t)(ok ? ng : 0) * 1024 + c * 64) + e2 * 16;
            cp16z(stg + OFF_WR_ + p * 16, src, ok ? 16u : 0u);
        }
        CP_COMMIT();
    };

    // ---- convert raw W -> quantized digit tiles (same-thread chunk) ----
    auto convert = [&](int c) {
        char* base = smem + (size_t)(c & 1) * STAGE_I8;
        int p  = tid;
        int nl = p >> 4;
        int e2 = p & 15;        // covers chunk-k positions 2e2, 2e2+1
        float4 w = *reinterpret_cast<const float4*>(base + OFF_WR_ + p * 16);
        int h0, l0, h1, l1;
        quant_split(w.y - w.x, SW_F, h0, l0);
        quant_split(w.w - w.z, SW_F, h1, l1);
        uint16_t hp = (uint16_t)((h0 & 0xFF) | ((h1 & 0xFF) << 8));
        uint16_t lp = (uint16_t)((l0 & 0xFF) | ((l1 & 0xFF) << 8));
        *reinterpret_cast<uint16_t*>(base + OFF_BH_ + nl * P48 + 2 * e2) = hp;
        *reinterpret_cast<uint16_t*>(base + OFF_BL_ + nl * P48 + 2 * e2) = lp;
    };

    // prologue
    issue(0);
    CP_WAIT0();
    convert(0);
    __syncthreads();

    for (int c = 0; c < 16; ++c) {
        if (c < 15) issue(c + 1);

        const uint32_t stg = sb + (uint32_t)(c & 1) * STAGE_I8;
        uint32_t ah[4][4], al[4][4], bh[2], bl[2];
#pragma unroll
        for (int mi = 0; mi < 4; ++mi)
            ldsm4(ah[mi], stg + OFF_AH_ + (uint32_t)((wm * 64 + mi * 16 + a_lrow) * P48 + a_lkb));
#pragma unroll
        for (int mi = 0; mi < 4; ++mi)
            ldsm4(al[mi], stg + OFF_AL_ + (uint32_t)((wm * 64 + mi * 16 + a_lrow) * P48 + a_lkb));
        ldsm2(bh, stg + OFF_BH_ + (uint32_t)(b_lrow * P48 + b_lkb));
        ldsm2(bl, stg + OFF_BL_ + (uint32_t)(b_lrow * P48 + b_lkb));

#pragma unroll
        for (int mi = 0; mi < 4; ++mi) imma(hh[mi],  ah[mi], bh[0], bh[1]);
#pragma unroll
        for (int mi = 0; mi < 4; ++mi) imma(mid[mi], ah[mi], bl[0], bl[1]);
#pragma unroll
        for (int mi = 0; mi < 4; ++mi) imma(mid[mi], al[mi], bh[0], bh[1]);
#pragma unroll
        for (int mi = 0; mi < 4; ++mi) imma(ll[mi],  al[mi], bl[0], bl[1]);

        if (c < 15) {
            CP_WAIT0();
            convert(c + 1);
        }
        __syncthreads();
    }

    // ---- epilogue: combine digits exactly, scale, add db, store ----
    {
        int colL = wn * 8 + 2 * (lane & 3);
        int col  = nbase + colL;
        float db0 = db_s[colL];
        float db1 = db_s[colL + 1];
#pragma unroll
        for (int mi = 0; mi < 4; ++mi) {
            int row = wm * 64 + mi * 16 + (lane >> 2);
#pragma unroll
            for (int h = 0; h < 2; ++h) {   // h=0: row, h=1: row+8 (regs 2,3)
                long long t0 = ((long long)hh[mi][2 * h] << 16) +
                               ((long long)mid[mi][2 * h] << 8) + ll[mi][2 * h];
                long long t1 = ((long long)hh[mi][2 * h + 1] << 16) +
                               ((long long)mid[mi][2 * h + 1] << 8) + ll[mi][2 * h + 1];
                float2 v = make_float2((float)t0 * INV_F + db0,
                                       (float)t1 * INV_F + db1);
                *reinterpret_cast<float2*>(&g_S[(size_t)(row + 8 * h) * NPAD + col]) = v;
            }
        }
    }
}

// ---------------------------------------------------------------------------
// Tree kernel: 8 subtrees per batch row (depth-3 roots), grid (8, 256).
// ---------------------------------------------------------------------------
__device__ __forceinline__ void sig2(float delta, float& p0, float& p1) {
    float dc = fminf(fmaxf(delta, -30.f), 30.f);
    float t = __expf(-dc);
    float r = __fdividef(1.f, 1.f + t);
    p1 = r;
    p0 = t * r;
}

__global__ void __launch_bounds__(256) tree_kernel(float* __restrict__ out) {
    __shared__ float bufA[1024];
    __shared__ float bufB[1024];
    const int r   = blockIdx.x;
    const int b   = blockIdx.y;
    const int tid = threadIdx.x;
    const float* S = g_S + (size_t)b * NPAD;

    float P;
    {
        float p0, p1;
        sig2(S[0], p0, p1);                 P  = (r & 4) ? p1 : p0;
        sig2(S[1 + (r >> 2)], p0, p1);      P *= (r & 2) ? p1 : p0;
        sig2(S[3 + (r >> 1)], p0, p1);      P *= (r & 1) ? p1 : p0;
    }
    if (tid == 0) bufA[0] = P;
    __syncthreads();

    float* cur = bufA;
    float* nxt = bufB;
    int L = 1;
#pragma unroll
    for (int d = 3; d <= 12; ++d) {
        const int base = (1 << d) - 1 + r * L;
        for (int i = tid; i < L; i += 256) {
            float p0, p1;
            sig2(S[base + i], p0, p1);
            float cc = cur[i];
            nxt[2 * i]     = cc * p0;
            nxt[2 * i + 1] = cc * p1;
        }
        __syncthreads();
        float* t = cur; cur = nxt; nxt = t;
        L <<= 1;
    }

    float2* orow = reinterpret_cast<float2*>(out + (size_t)b * NPAD) + r * 1024;
    const int base = 8191 + r * 1024;
    for (int i = tid; i < 1024; i += 256) {
        float p0, p1;
        sig2(S[base + i], p0, p1);
        float cc = cur[i];
        orow[i] = make_float2(cc * p0, cc * p1);
    }
}

// ---------------------------------------------------------------------------
// Launch
// ---------------------------------------------------------------------------
extern "C" void kernel_launch(void* const* d_in, const int* in_sizes, int n_in,
                              void* d_out, int out_size) {
    const float* x    = (const float*)d_in[0];
    const float* W    = (const float*)d_in[1];
    const float* bvec = (const float*)d_in[2];
    float* out = (float*)d_out;

    cudaFuncSetAttribute(gemm_i8, cudaFuncAttributeMaxDynamicSharedMemorySize, GEMM_SMEM);

    prep_kernel<<<128, 256>>>(x);
    gemm_i8<<<NPAD / NB, 512, GEMM_SMEM>>>(W, bvec);
    tree_kernel<<<dim3(8, BATCH), 256>>>(out);
}

// round 9
// speedup vs baseline: 1.6730x; 1.6730x over previous
#include <cuda_runtime.h>
#include <cuda_fp16.h>
#include <cstdint>

#define BATCH  256
#define EDIM   512
#define NNODES 16383
#define NPAD   16384

// ---------------------------------------------------------------------------
// Scratch (static device globals: allocation-free rule)
// ---------------------------------------------------------------------------
__device__ __half g_A[BATCH * 1024];   // [xh(512) | xl(512)] per batch row (fp16)
__device__ float  g_S[BATCH * NPAD];   // delta logits

// ---------------------------------------------------------------------------
// Prep A: split x into fp16 high/low parts (float4 per thread)
// ---------------------------------------------------------------------------
__global__ void prepA_kernel(const float* __restrict__ x) {
    int idx = blockIdx.x * blockDim.x + threadIdx.x;   // 0 .. 32767 float4s
    int b  = idx >> 7;
    int e4 = (idx & 127) * 4;
    float4 v = reinterpret_cast<const float4*>(x)[idx];
    __half h0 = __float2half_rn(v.x), h1 = __float2half_rn(v.y);
    __half h2 = __float2half_rn(v.z), h3 = __float2half_rn(v.w);
    __half l0 = __float2half_rn(v.x - __half2float(h0));
    __half l1 = __float2half_rn(v.y - __half2float(h1));
    __half l2 = __float2half_rn(v.z - __half2float(h2));
    __half l3 = __float2half_rn(v.w - __half2float(h3));
    __half2* hd = reinterpret_cast<__half2*>(g_A + b * 1024 + e4);
    hd[0] = __halves2half2(h0, h1);
    hd[1] = __halves2half2(h2, h3);
    __half2* ld = reinterpret_cast<__half2*>(g_A + b * 1024 + 512 + e4);
    ld[0] = __halves2half2(l0, l1);
    ld[1] = __halves2half2(l2, l3);
}

// ---------------------------------------------------------------------------
// cp.async + ldmatrix helpers
// ---------------------------------------------------------------------------
__device__ __forceinline__ uint32_t smem_u32(const void* p) {
    uint32_t a;
    asm("{ .reg .u64 t; cvta.to.shared.u64 t, %1; cvt.u32.u64 %0, t; }" : "=r"(a) : "l"(p));
    return a;
}
__device__ __forceinline__ void cp16(uint32_t dst, const void* src) {
    asm volatile("cp.async.ca.shared.global [%0], [%1], 16;" :: "r"(dst), "l"(src));
}
__device__ __forceinline__ void cp16z(uint32_t dst, const void* src, uint32_t src_bytes) {
    asm volatile("cp.async.ca.shared.global [%0], [%1], 16, %2;"
                 :: "r"(dst), "l"(src), "r"(src_bytes));
}
#define CP_COMMIT() asm volatile("cp.async.commit_group;" ::: "memory")
#define CP_WAIT0()  asm volatile("cp.async.wait_group 0;" ::: "memory")

__device__ __forceinline__ void ldsm4(uint32_t* r, uint32_t addr) {
    asm volatile("ldmatrix.sync.aligned.m8n8.x4.shared.b16 {%0,%1,%2,%3}, [%4];"
                 : "=r"(r[0]), "=r"(r[1]), "=r"(r[2]), "=r"(r[3]) : "r"(addr));
}

__device__ __forceinline__ void mma16816(float* acc, const uint32_t* a, uint32_t b0, uint32_t b1) {
    asm volatile(
        "mma.sync.aligned.m16n8k16.row.col.f32.f16.f16.f32 "
        "{%0,%1,%2,%3}, {%4,%5,%6,%7}, {%8,%9}, {%0,%1,%2,%3};\n"
        : "+f"(acc[0]), "+f"(acc[1]), "+f"(acc[2]), "+f"(acc[3])
        : "r"(a[0]), "r"(a[1]), "r"(a[2]), "r"(a[3]), "r"(b0), "r"(b1));
}

// ---------------------------------------------------------------------------
// Fused GEMM: S[m][n] = (xh+xl) . fp16(dW) + db   (2 mma phases)
//   512 threads / 16 warps; warp tile 64(M) x 32(N). Block M=256 x N=128.
//   K = 512 fp32 in 16 chunks of 32; 2-stage cp.async ring; W converted
//   in-SMEM to fp16; fragments via ldmatrix.
// ---------------------------------------------------------------------------
#define STAGE     83968
#define OFF_AH    0          // 256 x 40 fp16 (pitch 80 B) = 20480 B
#define OFF_AL    20480
#define OFF_BH    40960      // 128 x 40 fp16 = 10240 B
#define OFF_WR    51200      // raw W floats: 128 nodes x 64 floats x 4 B = 32768 B
#define OFF_DB    (2 * STAGE)            // 167936
#define GEMM_SMEM (OFF_DB + 512)         // 168448 B

__global__ void __launch_bounds__(512) gemm_f(const float* __restrict__ W,
                                              const float* __restrict__ bvec) {
    extern __shared__ char smem[];
    const uint32_t sb = smem_u32(smem);
    const int tid  = threadIdx.x;
    const int lane = tid & 31;
    const int warp = tid >> 5;
    const int wm   = warp >> 2;   // 0..3 -> M base wm*64
    const int wn   = warp & 3;    // 0..3 -> N base wn*32
    const int ntile = blockIdx.x * 128;

    float* db_s = reinterpret_cast<float*>(smem + OFF_DB);
    if (tid < 128) {
        int col = ntile + tid;
        db_s[tid] = (col < NNODES) ? (bvec[2 * col + 1] - bvec[2 * col]) : 0.f;
    }

    float acc[4][4][4];
#pragma unroll
    for (int mi = 0; mi < 4; ++mi)
#pragma unroll
        for (int ni = 0; ni < 4; ++ni)
#pragma unroll
            for (int q = 0; q < 4; ++q) acc[mi][ni][q] = 0.f;

    // ldmatrix per-lane address components
    const int a_row = wm * 64 + (lane & 7) + ((lane >> 3) & 1) * 8;
    const int a_col = (lane >> 4) * 8;
    const int b_row = wn * 32 + (lane & 7) + ((lane >> 4) & 1) * 8;
    const int b_col = ((lane >> 3) & 1) * 8;

    // ---- issue async loads for chunk c into stage c&1 ----
    auto issue = [&](int c) {
        const uint32_t stg = sb + (uint32_t)(c & 1) * STAGE;
        // A tiles: 256 rows x 32 fp16 (4 x 16 B) x {hi,lo} = 2048 chunks, 4/thread
#pragma unroll
        for (int j = 0; j < 4; ++j) {
            int u = tid + 512 * j;
            int h = u >> 10;          // 0=hi, 1=lo
            int v = u & 1023;
            int row = v >> 2;
            int c16 = v & 3;
            const char* src = reinterpret_cast<const char*>(
                g_A + (size_t)row * 1024 + h * 512 + c * 32) + c16 * 16;
            cp16(stg + (h ? OFF_AL : OFF_AH) + row * 80 + c16 * 16, src);
        }
        // raw W: 128 nodes x 64 consecutive floats (16 x 16 B) = 2048 chunks, 4/thread
#pragma unroll
        for (int j = 0; j < 4; ++j) {
            int p  = tid + 512 * j;
            int nl = p >> 4;
            int e2 = p & 15;
            int ng = ntile + nl;
            int ok = (ng < NNODES);
            const char* src = reinterpret_cast<const char*>(
                W + (size_t)(ok ? ng : 0) * 1024 + c * 64) + e2 * 16;
            cp16z(stg + OFF_WR + p * 16, src, ok ? 16u : 0u);
        }
        CP_COMMIT();
    };

    // ---- convert raw W floats -> fp16 B tile (same-thread chunks) ----
    auto convert = [&](int c) {
        char* base = smem + (size_t)(c & 1) * STAGE;
#pragma unroll
        for (int j = 0; j < 4; ++j) {
            int p  = tid + 512 * j;
            int nl = p >> 4;
            int e2 = p & 15;
            float4 w = *reinterpret_cast<const float4*>(base + OFF_WR + p * 16);
            __half h0 = __float2half_rn(w.y - w.x);
            __half h1 = __float2half_rn(w.w - w.z);
            *reinterpret_cast<__half2*>(base + OFF_BH + nl * 80 + e2 * 4) =
                __halves2half2(h0, h1);
        }
    };

    // prologue: stage 0
    issue(0);
    CP_WAIT0();
    convert(0);
    __syncthreads();

    for (int c = 0; c < 16; ++c) {
        if (c < 15) issue(c + 1);

        // ---- MMAs on stage c&1 ----
        const uint32_t stg = sb + (uint32_t)(c & 1) * STAGE;
#pragma unroll
        for (int ks = 0; ks < 32; ks += 16) {
            const uint32_t a_addr = stg + (uint32_t)(a_row * 80 + (ks + a_col) * 2);
            const uint32_t b_addr = stg + (uint32_t)(b_row * 80 + (ks + b_col) * 2);

            uint32_t ah[4][4], bh[2][4];
#pragma unroll
            for (int mi = 0; mi < 4; ++mi) ldsm4(ah[mi], a_addr + OFF_AH + mi * 16 * 80);
#pragma unroll
            for (int q = 0; q < 2; ++q)    ldsm4(bh[q], b_addr + OFF_BH + q * 16 * 80);
#pragma unroll
            for (int mi = 0; mi < 4; ++mi)
#pragma unroll
                for (int ni = 0; ni < 4; ++ni)
                    mma16816(acc[mi][ni], ah[mi], bh[ni >> 1][(ni & 1) * 2],
                             bh[ni >> 1][(ni & 1) * 2 + 1]);

            uint32_t al[4][4];
#pragma unroll
            for (int mi = 0; mi < 4; ++mi) ldsm4(al[mi], a_addr + OFF_AL + mi * 16 * 80);
#pragma unroll
            for (int mi = 0; mi < 4; ++mi)
#pragma unroll
                for (int ni = 0; ni < 4; ++ni)
                    mma16816(acc[mi][ni], al[mi], bh[ni >> 1][(ni & 1) * 2],
                             bh[ni >> 1][(ni & 1) * 2 + 1]);
        }

        if (c < 15) {
            CP_WAIT0();
            convert(c + 1);
        }
        __syncthreads();
    }

    // ---- epilogue: add db, store fp32 delta ----
#pragma unroll
    for (int ni = 0; ni < 4; ++ni) {
        int colL = wn * 32 + ni * 8 + ((lane & 3) << 1);
        int col  = ntile + colL;
        float db0 = db_s[colL];
        float db1 = db_s[colL + 1];
#pragma unroll
        for (int mi = 0; mi < 4; ++mi) {
            int row = wm * 64 + mi * 16 + (lane >> 2);
            float2 v0 = make_float2(acc[mi][ni][0] + db0, acc[mi][ni][1] + db1);
            float2 v1 = make_float2(acc[mi][ni][2] + db0, acc[mi][ni][3] + db1);
            *reinterpret_cast<float2*>(&g_S[(size_t)row * NPAD + col]) = v0;
            *reinterpret_cast<float2*>(&g_S[(size_t)(row + 8) * NPAD + col]) = v1;
        }
    }
}

// ---------------------------------------------------------------------------
// Tree kernel: 8 subtrees per batch row (depth-3 roots), grid (8, 256).
// ---------------------------------------------------------------------------
__device__ __forceinline__ void sig2(float delta, float& p0, float& p1) {
    float dc = fminf(fmaxf(delta, -30.f), 30.f);
    float t = __expf(-dc);
    float r = __fdividef(1.f, 1.f + t);
    p1 = r;
    p0 = t * r;
}

__global__ void __launch_bounds__(256) tree_kernel(float* __restrict__ out) {
    __shared__ float bufA[1024];
    __shared__ float bufB[1024];
    const int r   = blockIdx.x;
    const int b   = blockIdx.y;
    const int tid = threadIdx.x;
    const float* S = g_S + (size_t)b * NPAD;

    float P;
    {
        float p0, p1;
        sig2(S[0], p0, p1);                 P  = (r & 4) ? p1 : p0;
        sig2(S[1 + (r >> 2)], p0, p1);      P *= (r & 2) ? p1 : p0;
        sig2(S[3 + (r >> 1)], p0, p1);      P *= (r & 1) ? p1 : p0;
    }
    if (tid == 0) bufA[0] = P;
    __syncthreads();

    float* cur = bufA;
    float* nxt = bufB;
    int L = 1;
#pragma unroll
    for (int d = 3; d <= 12; ++d) {
        const int base = (1 << d) - 1 + r * L;
        for (int i = tid; i < L; i += 256) {
            float p0, p1;
            sig2(S[base + i], p0, p1);
            float cc = cur[i];
            nxt[2 * i]     = cc * p0;
            nxt[2 * i + 1] = cc * p1;
        }
        __syncthreads();
        float* t = cur; cur = nxt; nxt = t;
        L <<= 1;
    }

    float2* orow = reinterpret_cast<float2*>(out + (size_t)b * NPAD) + r * 1024;
    const int base = 8191 + r * 1024;
    for (int i = tid; i < 1024; i += 256) {
        float p0, p1;
        sig2(S[base + i], p0, p1);
        float cc = cur[i];
        orow[i] = make_float2(cc * p0, cc * p1);
    }
}

// ---------------------------------------------------------------------------
// Launch
// ---------------------------------------------------------------------------
extern "C" void kernel_launch(void* const* d_in, const int* in_sizes, int n_in,
                              void* d_out, int out_size) {
    const float* x    = (const float*)d_in[0];
    const float* W    = (const float*)d_in[1];
    const float* bvec = (const float*)d_in[2];
    float* out = (float*)d_out;

    cudaFuncSetAttribute(gemm_f, cudaFuncAttributeMaxDynamicSharedMemorySize, GEMM_SMEM);

    prepA_kernel<<<128, 256>>>(x);
    gemm_f<<<128, 512, GEMM_SMEM>>>(W, bvec);
    tree_kernel<<<dim3(8, BATCH), 256>>>(out);
}

// round 10
// speedup vs baseline: 1.8604x; 1.1120x over previous
#include <cuda_runtime.h>
#include <cuda_fp16.h>
#include <cstdint>

#define BATCH  256
#define EDIM   512
#define NNODES 16383
#define NPAD   16384

// ---------------------------------------------------------------------------
// Scratch (static device globals: allocation-free rule)
// ---------------------------------------------------------------------------
__device__ float g_S[BATCH * NPAD];   // delta logits

// ---------------------------------------------------------------------------
// cp.async + ldmatrix helpers
// ---------------------------------------------------------------------------
__device__ __forceinline__ uint32_t smem_u32(const void* p) {
    uint32_t a;
    asm("{ .reg .u64 t; cvta.to.shared.u64 t, %1; cvt.u32.u64 %0, t; }" : "=r"(a) : "l"(p));
    return a;
}
__device__ __forceinline__ void cp16(uint32_t dst, const void* src) {
    asm volatile("cp.async.ca.shared.global [%0], [%1], 16;" :: "r"(dst), "l"(src));
}
__device__ __forceinline__ void cp16z(uint32_t dst, const void* src, uint32_t src_bytes) {
    asm volatile("cp.async.ca.shared.global [%0], [%1], 16, %2;"
                 :: "r"(dst), "l"(src), "r"(src_bytes));
}
#define CP_COMMIT() asm volatile("cp.async.commit_group;" ::: "memory")
#define CP_WAIT0()  asm volatile("cp.async.wait_group 0;" ::: "memory")

__device__ __forceinline__ void ldsm4(uint32_t* r, uint32_t addr) {
    asm volatile("ldmatrix.sync.aligned.m8n8.x4.shared.b16 {%0,%1,%2,%3}, [%4];"
                 : "=r"(r[0]), "=r"(r[1]), "=r"(r[2]), "=r"(r[3]) : "r"(addr));
}

__device__ __forceinline__ void mma16816(float* acc, const uint32_t* a, uint32_t b0, uint32_t b1) {
    asm volatile(
        "mma.sync.aligned.m16n8k16.row.col.f32.f16.f16.f32 "
        "{%0,%1,%2,%3}, {%4,%5,%6,%7}, {%8,%9}, {%0,%1,%2,%3};\n"
        : "+f"(acc[0]), "+f"(acc[1]), "+f"(acc[2]), "+f"(acc[3])
        : "r"(a[0]), "r"(a[1]), "r"(a[2]), "r"(a[3]), "r"(b0), "r"(b1));
}

// ---------------------------------------------------------------------------
// Fully-fused single-phase fp16 GEMM: S = fp16(x) . fp16(dW) + db
//   512 threads / 16 warps; warp tile 64(M) x 32(N). Block M=256 x N=128.
//   K = 512 in 16 chunks of 32. Per chunk: cp.async raw x + raw W f32
//   slices, convert both to fp16 tiles in SMEM, 1 mma phase (32 mma/warp).
//   2-stage ring. No separate prep kernel.
// ---------------------------------------------------------------------------
#define STAGE     96256
#define OFF_AT    0          // A fp16 tile: 256 x 40 (pitch 80 B) = 20480
#define OFF_BT    20480      // B fp16 tile: 128 x 40 = 10240
#define OFF_XR    30720      // raw x: 256 rows x 32 f32 = 32768
#define OFF_WR    63488      // raw W: 128 nodes x 64 f32 = 32768
#define OFF_DB    (2 * STAGE)            // 192512
#define GEMM_SMEM (OFF_DB + 512)         // 193024 B

__global__ void __launch_bounds__(512) gemm_f(const float* __restrict__ x,
                                              const float* __restrict__ W,
                                              const float* __restrict__ bvec) {
    extern __shared__ char smem[];
    const uint32_t sb = smem_u32(smem);
    const int tid  = threadIdx.x;
    const int lane = tid & 31;
    const int warp = tid >> 5;
    const int wm   = warp >> 2;   // 0..3 -> M base wm*64
    const int wn   = warp & 3;    // 0..3 -> N base wn*32
    const int ntile = blockIdx.x * 128;

    float* db_s = reinterpret_cast<float*>(smem + OFF_DB);
    if (tid < 128) {
        int col = ntile + tid;
        db_s[tid] = (col < NNODES) ? (bvec[2 * col + 1] - bvec[2 * col]) : 0.f;
    }

    float acc[4][4][4];
#pragma unroll
    for (int mi = 0; mi < 4; ++mi)
#pragma unroll
        for (int ni = 0; ni < 4; ++ni)
#pragma unroll
            for (int q = 0; q < 4; ++q) acc[mi][ni][q] = 0.f;

    // ldmatrix per-lane address components
    const int a_row = wm * 64 + (lane & 7) + ((lane >> 3) & 1) * 8;
    const int a_col = (lane >> 4) * 8;
    const int b_row = wn * 32 + (lane & 7) + ((lane >> 4) & 1) * 8;
    const int b_col = ((lane >> 3) & 1) * 8;

    // ---- issue async loads for chunk c into stage c&1 ----
    auto issue = [&](int c) {
        const uint32_t stg = sb + (uint32_t)(c & 1) * STAGE;
        // raw x: 256 rows x 32 f32 (8 x 16 B per row) = 2048 cp16, 4/thread
#pragma unroll
        for (int j = 0; j < 4; ++j) {
            int u  = tid + 512 * j;
            int row = u >> 3;
            int q8  = u & 7;
            const char* src = reinterpret_cast<const char*>(x) +
                              (size_t)row * 2048 + c * 128 + q8 * 16;
            cp16(stg + OFF_XR + u * 16, src);
        }
        // raw W: 128 nodes x 64 f32 (16 x 16 B) = 2048 cp16, 4/thread
#pragma unroll
        for (int j = 0; j < 4; ++j) {
            int p  = tid + 512 * j;
            int nl = p >> 4;
            int e2 = p & 15;
            int ng = ntile + nl;
            int ok = (ng < NNODES);
            const char* src = reinterpret_cast<const char*>(
                W + (size_t)(ok ? ng : 0) * 1024 + c * 64) + e2 * 16;
            cp16z(stg + OFF_WR + p * 16, src, ok ? 16u : 0u);
        }
        CP_COMMIT();
    };

    // ---- convert raw f32 -> fp16 tiles (same-thread chunks) ----
    auto convert = [&](int c) {
        char* base = smem + (size_t)(c & 1) * STAGE;
        // A: float4 u covers row u>>3, k q8*4..q8*4+3
#pragma unroll
        for (int j = 0; j < 4; ++j) {
            int u  = tid + 512 * j;
            int row = u >> 3;
            int q8  = u & 7;
            float4 v = *reinterpret_cast<const float4*>(base + OFF_XR + u * 16);
            __half2 p0 = __halves2half2(__float2half_rn(v.x), __float2half_rn(v.y));
            __half2 p1 = __halves2half2(__float2half_rn(v.z), __float2half_rn(v.w));
            __half2* dst = reinterpret_cast<__half2*>(base + OFF_AT + row * 80 + q8 * 8);
            dst[0] = p0;
            dst[1] = p1;
        }
        // W: float4 p covers node p>>4, k-pair (p&15)
#pragma unroll
        for (int j = 0; j < 4; ++j) {
            int p  = tid + 512 * j;
            int nl = p >> 4;
            int e2 = p & 15;
            float4 w = *reinterpret_cast<const float4*>(base + OFF_WR + p * 16);
            __half h0 = __float2half_rn(w.y - w.x);
            __half h1 = __float2half_rn(w.w - w.z);
            *reinterpret_cast<__half2*>(base + OFF_BT + nl * 80 + e2 * 4) =
                __halves2half2(h0, h1);
        }
    };

    // prologue: stage 0
    issue(0);
    CP_WAIT0();
    convert(0);
    __syncthreads();

    for (int c = 0; c < 16; ++c) {
        if (c < 15) issue(c + 1);

        // ---- MMAs on stage c&1 ----
        const uint32_t stg = sb + (uint32_t)(c & 1) * STAGE;
#pragma unroll
        for (int ks = 0; ks < 32; ks += 16) {
            const uint32_t a_addr = stg + (uint32_t)(a_row * 80 + (ks + a_col) * 2);
            const uint32_t b_addr = stg + (uint32_t)(b_row * 80 + (ks + b_col) * 2);

            uint32_t ah[4][4], bh[2][4];
#pragma unroll
            for (int mi = 0; mi < 4; ++mi) ldsm4(ah[mi], a_addr + OFF_AT + mi * 16 * 80);
#pragma unroll
            for (int q = 0; q < 2; ++q)    ldsm4(bh[q], b_addr + OFF_BT + q * 16 * 80);
#pragma unroll
            for (int mi = 0; mi < 4; ++mi)
#pragma unroll
                for (int ni = 0; ni < 4; ++ni)
                    mma16816(acc[mi][ni], ah[mi], bh[ni >> 1][(ni & 1) * 2],
                             bh[ni >> 1][(ni & 1) * 2 + 1]);
        }

        if (c < 15) {
            CP_WAIT0();
            convert(c + 1);
        }
        __syncthreads();
    }

    // ---- epilogue: add db, store fp32 delta ----
#pragma unroll
    for (int ni = 0; ni < 4; ++ni) {
        int colL = wn * 32 + ni * 8 + ((lane & 3) << 1);
        int col  = ntile + colL;
        float db0 = db_s[colL];
        float db1 = db_s[colL + 1];
#pragma unroll
        for (int mi = 0; mi < 4; ++mi) {
            int row = wm * 64 + mi * 16 + (lane >> 2);
            float2 v0 = make_float2(acc[mi][ni][0] + db0, acc[mi][ni][1] + db1);
            float2 v1 = make_float2(acc[mi][ni][2] + db0, acc[mi][ni][3] + db1);
            *reinterpret_cast<float2*>(&g_S[(size_t)row * NPAD + col]) = v0;
            *reinterpret_cast<float2*>(&g_S[(size_t)(row + 8) * NPAD + col]) = v1;
        }
    }
}

// ---------------------------------------------------------------------------
// Tree kernel: 8 subtrees per batch row (depth-3 roots), grid (8, 256).
// ---------------------------------------------------------------------------
__device__ __forceinline__ void sig2(float delta, float& p0, float& p1) {
    float dc = fminf(fmaxf(delta, -30.f), 30.f);
    float t = __expf(-dc);
    float r = __fdividef(1.f, 1.f + t);
    p1 = r;
    p0 = t * r;
}

__global__ void __launch_bounds__(256) tree_kernel(float* __restrict__ out) {
    __shared__ float bufA[1024];
    __shared__ float bufB[1024];
    const int r   = blockIdx.x;
    const int b   = blockIdx.y;
    const int tid = threadIdx.x;
    const float* S = g_S + (size_t)b * NPAD;

    float P;
    {
        float p0, p1;
        sig2(S[0], p0, p1);                 P  = (r & 4) ? p1 : p0;
        sig2(S[1 + (r >> 2)], p0, p1);      P *= (r & 2) ? p1 : p0;
        sig2(S[3 + (r >> 1)], p0, p1);      P *= (r & 1) ? p1 : p0;
    }
    if (tid == 0) bufA[0] = P;
    __syncthreads();

    float* cur = bufA;
    float* nxt = bufB;
    int L = 1;
#pragma unroll
    for (int d = 3; d <= 12; ++d) {
        const int base = (1 << d) - 1 + r * L;
        for (int i = tid; i < L; i += 256) {
            float p0, p1;
            sig2(S[base + i], p0, p1);
            float cc = cur[i];
            nxt[2 * i]     = cc * p0;
            nxt[2 * i + 1] = cc * p1;
        }
        __syncthreads();
        float* t = cur; cur = nxt; nxt = t;
        L <<= 1;
    }

    float2* orow = reinterpret_cast<float2*>(out + (size_t)b * NPAD) + r * 1024;
    const int base = 8191 + r * 1024;
    for (int i = tid; i < 1024; i += 256) {
        float p0, p1;
        sig2(S[base + i], p0, p1);
        float cc = cur[i];
        orow[i] = make_float2(cc * p0, cc * p1);
    }
}

// ---------------------------------------------------------------------------
// Launch
// ---------------------------------------------------------------------------
extern "C" void kernel_launch(void* const* d_in, const int* in_sizes, int n_in,
                              void* d_out, int out_size) {
    const float* x    = (const float*)d_in[0];
    const float* W    = (const float*)d_in[1];
    const float* bvec = (const float*)d_in[2];
    float* out = (float*)d_out;

    cudaFuncSetAttribute(gemm_f, cudaFuncAttributeMaxDynamicSharedMemorySize, GEMM_SMEM);

    gemm_f<<<128, 512, GEMM_SMEM>>>(x, W, bvec);
    tree_kernel<<<dim3(8, BATCH), 256>>>(out);
}

// round 13
// speedup vs baseline: 1.8712x; 1.0058x over previous
#include <cuda_runtime.h>
#include <cuda_fp16.h>
#include <cstdint>

#define BATCH  256
#define EDIM   512
#define NNODES 16383
#define NPAD   16384

// ---------------------------------------------------------------------------
// Scratch (static device globals: allocation-free rule)
// ---------------------------------------------------------------------------
__device__ __half g_X[BATCH * EDIM];  // x as fp16
__device__ float  g_S[BATCH * NPAD];  // delta logits

// ---------------------------------------------------------------------------
// Prep X: convert x to fp16 (8 floats -> one 16B store per thread)
// ---------------------------------------------------------------------------
__global__ void prepX_kernel(const float* __restrict__ x) {
    int idx = blockIdx.x * blockDim.x + threadIdx.x;   // 0..16383, 8 floats each
    const float4* src = reinterpret_cast<const float4*>(x) + idx * 2;
    float4 v0 = src[0];
    float4 v1 = src[1];
    __half2 h0 = __halves2half2(__float2half_rn(v0.x), __float2half_rn(v0.y));
    __half2 h1 = __halves2half2(__float2half_rn(v0.z), __float2half_rn(v0.w));
    __half2 h2 = __halves2half2(__float2half_rn(v1.x), __float2half_rn(v1.y));
    __half2 h3 = __halves2half2(__float2half_rn(v1.z), __float2half_rn(v1.w));
    uint4 pack;
    pack.x = *reinterpret_cast<uint32_t*>(&h0);
    pack.y = *reinterpret_cast<uint32_t*>(&h1);
    pack.z = *reinterpret_cast<uint32_t*>(&h2);
    pack.w = *reinterpret_cast<uint32_t*>(&h3);
    reinterpret_cast<uint4*>(g_X)[idx] = pack;
}

// ---------------------------------------------------------------------------
// cp.async + ldmatrix helpers
// ---------------------------------------------------------------------------
__device__ __forceinline__ uint32_t smem_u32(const void* p) {
    uint32_t a;
    asm("{ .reg .u64 t; cvta.to.shared.u64 t, %1; cvt.u32.u64 %0, t; }" : "=r"(a) : "l"(p));
    return a;
}
__device__ __forceinline__ void cp16(uint32_t dst, const void* src) {
    asm volatile("cp.async.ca.shared.global [%0], [%1], 16;" :: "r"(dst), "l"(src));
}
__device__ __forceinline__ void cp16z(uint32_t dst, const void* src, uint32_t src_bytes) {
    asm volatile("cp.async.ca.shared.global [%0], [%1], 16, %2;"
                 :: "r"(dst), "l"(src), "r"(src_bytes));
}
#define CP_COMMIT() asm volatile("cp.async.commit_group;" ::: "memory")
#define CP_WAIT0()  asm volatile("cp.async.wait_group 0;" ::: "memory")

__device__ __forceinline__ void ldsm4(uint32_t* r, uint32_t addr) {
    asm volatile("ldmatrix.sync.aligned.m8n8.x4.shared.b16 {%0,%1,%2,%3}, [%4];"
                 : "=r"(r[0]), "=r"(r[1]), "=r"(r[2]), "=r"(r[3]) : "r"(addr));
}

__device__ __forceinline__ void mma16816(float* acc, const uint32_t* a, uint32_t b0, uint32_t b1) {
    asm volatile(
        "mma.sync.aligned.m16n8k16.row.col.f32.f16.f16.f32 "
        "{%0,%1,%2,%3}, {%4,%5,%6,%7}, {%8,%9}, {%0,%1,%2,%3};\n"
        : "+f"(acc[0]), "+f"(acc[1]), "+f"(acc[2]), "+f"(acc[3])
        : "r"(a[0]), "r"(a[1]), "r"(a[2]), "r"(a[3]), "r"(b0), "r"(b1));
}

// ---------------------------------------------------------------------------
// Single-phase fp16 GEMM: S = fp16(x) . fp16(dW) + db
//   A loaded pre-converted (no in-loop A convert); W converted in-SMEM.
//   512 threads / 16 warps; warp tile 64(M) x 32(N). Block M=256 x N=128.
//   K = 512 in 16 chunks of 32; 2-stage cp.async ring.
// ---------------------------------------------------------------------------
#define STAGE     63488
#define OFF_AT    0          // A fp16 tile: 256 x 40 (pitch 80 B) = 20480
#define OFF_BT    20480      // B fp16 tile: 128 x 40 = 10240
#define OFF_WR    30720      // raw W: 128 nodes x 64 f32 = 32768
#define OFF_DB    (2 * STAGE)            // 126976
#define GEMM_SMEM (OFF_DB + 512)         // 127488 B

__global__ void __launch_bounds__(512) gemm_f(const float* __restrict__ W,
                                              const float* __restrict__ bvec) {
    extern __shared__ char smem[];
    const uint32_t sb = smem_u32(smem);
    const int tid  = threadIdx.x;
    const int lane = tid & 31;
    const int warp = tid >> 5;
    const int wm   = warp >> 2;   // 0..3 -> M base wm*64
    const int wn   = warp & 3;    // 0..3 -> N base wn*32
    const int ntile = blockIdx.x * 128;

    float* db_s = reinterpret_cast<float*>(smem + OFF_DB);
    if (tid < 128) {
        int col = ntile + tid;
        db_s[tid] = (col < NNODES) ? (bvec[2 * col + 1] - bvec[2 * col]) : 0.f;
    }

    float acc[4][4][4];
#pragma unroll
    for (int mi = 0; mi < 4; ++mi)
#pragma unroll
        for (int ni = 0; ni < 4; ++ni)
#pragma unroll
            for (int q = 0; q < 4; ++q) acc[mi][ni][q] = 0.f;

    // ldmatrix per-lane address components
    const int a_row = wm * 64 + (lane & 7) + ((lane >> 3) & 1) * 8;
    const int a_col = (lane >> 4) * 8;
    const int b_row = wn * 32 + (lane & 7) + ((lane >> 4) & 1) * 8;
    const int b_col = ((lane >> 3) & 1) * 8;

    // ---- issue async loads for chunk c into stage c&1 ----
    auto issue = [&](int c) {
        const uint32_t stg = sb + (uint32_t)(c & 1) * STAGE;
        // A fp16: 256 rows x 32 fp16 (64 B = 4 x 16 B) = 1024 cp16, 2/thread
#pragma unroll
        for (int j = 0; j < 2; ++j) {
            int u = tid + 512 * j;
            int row = u >> 2;
            int c16 = u & 3;
            const char* src = reinterpret_cast<const char*>(
                g_X + (size_t)row * EDIM + c * 32) + c16 * 16;
            cp16(stg + OFF_AT + row * 80 + c16 * 16, src);
        }
        // raw W: 128 nodes x 64 f32 (16 x 16 B) = 2048 cp16, 4/thread
#pragma unroll
        for (int j = 0; j < 4; ++j) {
            int p  = tid + 512 * j;
            int nl = p >> 4;
            int e2 = p & 15;
            int ng = ntile + nl;
            int ok = (ng < NNODES);
            const char* src = reinterpret_cast<const char*>(
                W + (size_t)(ok ? ng : 0) * 1024 + c * 64) + e2 * 16;
            cp16z(stg + OFF_WR + p * 16, src, ok ? 16u : 0u);
        }
        CP_COMMIT();
    };

    // ---- convert raw W f32 -> fp16 B tile (same-thread chunks) ----
    auto convert = [&](int c) {
        char* base = smem + (size_t)(c & 1) * STAGE;
#pragma unroll
        for (int j = 0; j < 4; ++j) {
            int p  = tid + 512 * j;
            int nl = p >> 4;
            int e2 = p & 15;
            float4 w = *reinterpret_cast<const float4*>(base + OFF_WR + p * 16);
            __half h0 = __float2half_rn(w.y - w.x);
            __half h1 = __float2half_rn(w.w - w.z);
            *reinterpret_cast<__half2*>(base + OFF_BT + nl * 80 + e2 * 4) =
                __halves2half2(h0, h1);
        }
    };

    // prologue: stage 0
    issue(0);
    CP_WAIT0();
    convert(0);
    __syncthreads();

    for (int c = 0; c < 16; ++c) {
        if (c < 15) issue(c + 1);

        // ---- MMAs on stage c&1 ----
        const uint32_t stg = sb + (uint32_t)(c & 1) * STAGE;
#pragma unroll
        for (int ks = 0; ks < 32; ks += 16) {
            const uint32_t a_addr = stg + (uint32_t)(a_row * 80 + (ks + a_col) * 2);
            const uint32_t b_addr = stg + (uint32_t)(b_row * 80 + (ks + b_col) * 2);

            uint32_t ah[4][4], bh[2][4];
#pragma unroll
            for (int mi = 0; mi < 4; ++mi) ldsm4(ah[mi], a_addr + OFF_AT + mi * 16 * 80);
#pragma unroll
            for (int q = 0; q < 2; ++q)    ldsm4(bh[q], b_addr + OFF_BT + q * 16 * 80);
#pragma unroll
            for (int mi = 0; mi < 4; ++mi)
#pragma unroll
                for (int ni = 0; ni < 4; ++ni)
                    mma16816(acc[mi][ni], ah[mi], bh[ni >> 1][(ni & 1) * 2],
                             bh[ni >> 1][(ni & 1) * 2 + 1]);
        }

        if (c < 15) {
            CP_WAIT0();
            convert(c + 1);
        }
        __syncthreads();
    }

    // ---- epilogue: add db, store fp32 delta ----
#pragma unroll
    for (int ni = 0; ni < 4; ++ni) {
        int colL = wn * 32 + ni * 8 + ((lane & 3) << 1);
        int col  = ntile + colL;
        float db0 = db_s[colL];
        float db1 = db_s[colL + 1];
#pragma unroll
        for (int mi = 0; mi < 4; ++mi) {
            int row = wm * 64 + mi * 16 + (lane >> 2);
            float2 v0 = make_float2(acc[mi][ni][0] + db0, acc[mi][ni][1] + db1);
            float2 v1 = make_float2(acc[mi][ni][2] + db0, acc[mi][ni][3] + db1);
            *reinterpret_cast<float2*>(&g_S[(size_t)row * NPAD + col]) = v0;
            *reinterpret_cast<float2*>(&g_S[(size_t)(row + 8) * NPAD + col]) = v1;
        }
    }
}

// ---------------------------------------------------------------------------
// Warp-autonomous tree: each warp owns a depth-8 subtree (64 leaves).
// No smem, no barriers. Grid (32, 256), block 256 = 8 warps.
// ---------------------------------------------------------------------------
__device__ __forceinline__ void sig2(float delta, float& p0, float& p1) {
    float dc = fminf(fmaxf(delta, -30.f), 30.f);
    float t = __expf(-dc);
    float r = __fdividef(1.f, 1.f + t);
    p1 = r;
    p0 = t * r;
}

__global__ void __launch_bounds__(256) tree_kernel(float* __restrict__ out) {
    const int warp = threadIdx.x >> 5;
    const int lane = threadIdx.x & 31;
    const int t    = blockIdx.x * 8 + warp;   // depth-8 subtree index 0..255
    const int b    = blockIdx.y;              // batch row
    const float* S = g_S + (size_t)b * NPAD;

    // ---- path prefix through depths 0..7 (lane d computes ancestor d) ----
    float v = 1.f;
    if (lane < 8) {
        int d    = lane;
        int node = ((256 + t) >> (8 - d)) - 1;
        int bit  = (t >> (7 - d)) & 1;
        float p0, p1;
        sig2(S[node], p0, p1);
        v = bit ? p1 : p0;
    }
    v *= __shfl_xor_sync(0xFFFFFFFFu, v, 1);
    v *= __shfl_xor_sync(0xFFFFFFFFu, v, 2);
    v *= __shfl_xor_sync(0xFFFFFFFFu, v, 4);
    float cur = __shfl_sync(0xFFFFFFFFu, v, 0);   // prefix at depth-8 node t

    // ---- expand depths 8..12 via shuffles ----
#pragma unroll
    for (int k = 0; k < 5; ++k) {
        const int L    = 1 << k;                              // nodes this level
        const int base = ((1 << (8 + k)) - 1) + t * L;
        float p0, p1;
        sig2(S[base + (lane < L ? lane : 0)], p0, p1);        // lanes >= L: dummy
        int parent = lane >> 1;
        float c  = __shfl_sync(0xFFFFFFFFu, cur, parent);
        float a0 = __shfl_sync(0xFFFFFFFFu, p0,  parent);
        float a1 = __shfl_sync(0xFFFFFFFFu, p1,  parent);
        cur = c * ((lane & 1) ? a1 : a0);                     // valid for lane < 2L
    }

    // ---- depth 13: 32 nodes, write 64 leaves ----
    const int nbase = 8191 + t * 32;
    float p0, p1;
    sig2(S[nbase + lane], p0, p1);
    float2 leaf = make_float2(cur * p0, cur * p1);
    *reinterpret_cast<float2*>(out + (size_t)b * NPAD + t * 64 + lane * 2) = leaf;
}

// ---------------------------------------------------------------------------
// Launch
// ---------------------------------------------------------------------------
extern "C" void kernel_launch(void* const* d_in, const int* in_sizes, int n_in,
                              void* d_out, int out_size) {
    const float* x    = (const float*)d_in[0];
    const float* W    = (const float*)d_in[1];
    const float* bvec = (const float*)d_in[2];
    float* out = (float*)d_out;

    cudaFuncSetAttribute(gemm_f, cudaFuncAttributeMaxDynamicSharedMemorySize, GEMM_SMEM);

    prepX_kernel<<<64, 256>>>(x);
    gemm_f<<<128, 512, GEMM_SMEM>>>(W, bvec);
    tree_kernel<<<dim3(32, BATCH), 256>>>(out);
}